// round 10
// baseline (speedup 1.0000x reference)
#include <cuda_runtime.h>
#include <math.h>

#define NM 64
#define NA 24
#define NP 276
#define NPPAD 288
#define NT 6000
#define NTPAD 6016
#define QV 0.22360679774997896f
#define KE 0.016666666666666666f

#define G1_TT 94        // t-tiles of 64 (fused gemm1+epilogue)
#define G2_PT 3         // p-tiles of 128 (PPAD 384)
#define G2_KS 98        // t-splits, chunk 64 (8 k-tiles of 8)
#define G2_PPAD 384

typedef unsigned long long u64;

// ---------------- static device scratch ----------------
__device__ float g_qxs[NM * NP];
__device__ float g_xs3[NM * NP];
__device__ float g_nq[NM];
__device__ float g_qxsTd[NPPAD * 128];         // qxs transposed + dup [p][2m]
__device__ float g_nt[NTPAD];
__device__ float g_ct[NTPAD];
__device__ float g_aT[NTPAD * 128];            // (q a) transposed + dup [t][2m]
__device__ float g_bT[NTPAD * 128];
__device__ float g_Ep[G1_TT * NM];
__device__ float g_sa[G1_TT * NM];
__device__ float g_F2[G2_KS * NM * G2_PPAD];

__device__ __forceinline__ void ffma2(u64& c, u64 a, u64 b) {
    asm("fma.rn.f32x2 %0, %1, %2, %0;" : "+l"(c) : "l"(a), "l"(b));
}
__device__ __forceinline__ float2 upk(u64 v) {
    float2 f;
    asm("mov.b64 {%0, %1}, %2;" : "=f"(f.x), "=f"(f.y) : "l"(v));
    return f;
}
__device__ __forceinline__ void cp16(void* smem, const void* gptr, int bytes) {
    unsigned s = (unsigned)__cvta_generic_to_shared(smem);
    asm volatile("cp.async.ca.shared.global [%0], [%1], 16, %2;\n"
                 :: "r"(s), "l"(gptr), "r"(bytes));
}
__device__ __forceinline__ void cp_commit() {
    asm volatile("cp.async.commit_group;\n" ::: "memory");
}
__device__ __forceinline__ void cp_wait0() {
    asm volatile("cp.async.wait_group 0;\n" ::: "memory");
}

__device__ __forceinline__ void pair_ij(int p, int& i, int& j) {
    int ii = (int)((1.0f + sqrtf(1.0f + 8.0f * (float)p)) * 0.5f);
    while (ii * (ii - 1) / 2 > p) ii--;
    while ((ii + 1) * ii / 2 <= p) ii++;
    i = ii;
    j = p - ii * (ii - 1) / 2;
}

// ---------------- fused prep ----------------
__global__ void prep_kernel(const float* __restrict__ Rs,
                            const float* __restrict__ xt,
                            const float* __restrict__ jx) {
    const int tid = threadIdx.x;
    if (blockIdx.x < NM) {
        __shared__ float red[256];
        const int m = blockIdx.x;
        float ssum = 0.0f;
        #pragma unroll
        for (int rep = 0; rep < 2; rep++) {
            int p = tid + 256 * rep;
            if (p < NP) {
                int i, j;
                pair_ij(p, i, j);
                float dx = Rs[(m * NA + i) * 3 + 0] - Rs[(m * NA + j) * 3 + 0];
                float dy = Rs[(m * NA + i) * 3 + 1] - Rs[(m * NA + j) * 3 + 1];
                float dz = Rs[(m * NA + i) * 3 + 2] - Rs[(m * NA + j) * 3 + 2];
                float d = sqrtf(dx * dx + dy * dy + dz * dz);
                float xs = 1.0f / d;
                float qv = QV * xs;
                g_qxs[m * NP + p] = qv;
                g_xs3[m * NP + p] = xs * xs * xs;
                *(float2*)&g_qxsTd[p * 128 + 2 * m] = make_float2(qv, qv);
                ssum += qv * qv;
            } else if (p < NPPAD) {
                *(float2*)&g_qxsTd[p * 128 + 2 * m] = make_float2(0.0f, 0.0f);
            }
        }
        red[tid] = ssum;
        __syncthreads();
        if (tid < 32) {
            float s = red[tid];
            #pragma unroll
            for (int k = 1; k < 8; k++) s += red[tid + 32 * k];
            #pragma unroll
            for (int o = 16; o > 0; o >>= 1) s += __shfl_xor_sync(0xffffffffu, s, o);
            if (tid == 0) g_nq[m] = s;
        }
        return;
    }
    int w = ((blockIdx.x - NM) * blockDim.x + tid) >> 5;
    int lane = tid & 31;
    if (w >= NTPAD) return;
    if (w >= NT) {
        if (lane == 0) { g_nt[w] = 0.0f; g_ct[w] = 0.0f; }
        return;
    }
    const float* xr = xt + (size_t)w * NP;
    const float* jr = jx + (size_t)w * NP;
    float sn = 0.0f, sc = 0.0f;
    #pragma unroll
    for (int k = 0; k < 9; k++) {
        int p = lane + 32 * k;
        if (p < NP) {
            float x = xr[p];
            sn = fmaf(x, x, sn);
            sc = fmaf(x, jr[p], sc);
        }
    }
    #pragma unroll
    for (int o = 16; o > 0; o >>= 1) {
        sn += __shfl_xor_sync(0xffffffffu, sn, o);
        sc += __shfl_xor_sync(0xffffffffu, sc, o);
    }
    if (lane == 0) {
        g_nt[w] = QV * QV * sn;
        g_ct[w] = QV * sc;
    }
}

// ---------------- fused GEMM1 + epilogue: 256 thr, tile 64m x 64t, full K=288 ----------------
// frag: 8m (warp-uniform -> A broadcast) x 2t (t-pair packed in f32x2 lanes)
__global__ __launch_bounds__(256)
void gemm1f_kernel(const float* __restrict__ xt, const float* __restrict__ jx) {
    __shared__ float As[2][16 * 128];   // dup A [k][2m]  (16 KB)
    __shared__ float Bx[2][16 * 66];    // [k][t], pad 66  (8.25 KB)
    __shared__ float Bj[2][16 * 66];

    const int tid = threadIdx.x;
    const int tx = tid & 31;            // t-pair at 2*tx
    const int ty = tid >> 5;            // 8 m at 8*ty (warp-uniform)
    const int t0 = blockIdx.x * 64;
    const int NKT = 18;                 // 18 k-tiles of 16

    const int lbt = tid >> 2;           // B loader: t row 0..63
    const int lbc = tid & 3;            // k 4-group 0..3

    u64 acc1[8], acc2[8];               // [mi], lanes = t-pair
    #pragma unroll
    for (int i = 0; i < 8; i++) { acc1[i] = 0ull; acc2[i] = 0ull; }

    float4 xv, jv;

    auto cpA = [&](int kt, int buf) {
        int k0 = kt * 16;
        #pragma unroll
        for (int c = 0; c < 2; c++) {
            int idx = tid + 256 * c;
            int row = idx >> 5, col = idx & 31;
            cp16(&As[buf][row * 128 + col * 4], &g_qxsTd[(k0 + row) * 128 + col * 4], 16);
        }
        cp_commit();
    };
    auto ldgB = [&](int kt) {
        int k0 = kt * 16;
        int kk = k0 + 4 * lbc;
        int tg = t0 + lbt;
        xv = make_float4(0.f, 0.f, 0.f, 0.f);
        jv = make_float4(0.f, 0.f, 0.f, 0.f);
        if (tg < NT && kk < NP) {
            xv = *(const float4*)&xt[(size_t)tg * NP + kk];
            jv = *(const float4*)&jx[(size_t)tg * NP + kk];
        }
    };
    auto stsB = [&](int buf) {
        Bx[buf][(4 * lbc + 0) * 66 + lbt] = xv.x;
        Bx[buf][(4 * lbc + 1) * 66 + lbt] = xv.y;
        Bx[buf][(4 * lbc + 2) * 66 + lbt] = xv.z;
        Bx[buf][(4 * lbc + 3) * 66 + lbt] = xv.w;
        Bj[buf][(4 * lbc + 0) * 66 + lbt] = jv.x;
        Bj[buf][(4 * lbc + 1) * 66 + lbt] = jv.y;
        Bj[buf][(4 * lbc + 2) * 66 + lbt] = jv.z;
        Bj[buf][(4 * lbc + 3) * 66 + lbt] = jv.w;
    };

    ldgB(0);
    cpA(0, 0);
    stsB(0);
    ldgB(1);
    cp_wait0();
    __syncthreads();

    for (int kt = 0; kt < NKT; kt++) {
        const int cur = kt & 1;
        if (kt + 1 < NKT) {
            stsB(cur ^ 1);
            cpA(kt + 1, cur ^ 1);
        }
        if (kt + 2 < NKT) ldgB(kt + 2);

        #pragma unroll
        for (int k = 0; k < 16; k++) {
            // A: 8 m duplicated = 16 floats, warp-uniform (broadcast)
            ulonglong2 a0 = *(const ulonglong2*)&As[cur][k * 128 + 16 * ty];
            ulonglong2 a1 = *(const ulonglong2*)&As[cur][k * 128 + 16 * ty + 4];
            ulonglong2 a2 = *(const ulonglong2*)&As[cur][k * 128 + 16 * ty + 8];
            ulonglong2 a3 = *(const ulonglong2*)&As[cur][k * 128 + 16 * ty + 12];
            // B: one t-pair per thread
            u64 X = *(const u64*)&Bx[cur][k * 66 + 2 * tx];
            u64 J = *(const u64*)&Bj[cur][k * 66 + 2 * tx];
            u64 Ap[8] = {a0.x, a0.y, a1.x, a1.y, a2.x, a2.y, a3.x, a3.y};
            #pragma unroll
            for (int mi = 0; mi < 8; mi++) {
                ffma2(acc1[mi], Ap[mi], X);
                ffma2(acc2[mi], Ap[mi], J);
            }
        }
        if (kt + 1 < NKT) cp_wait0();
        __syncthreads();
    }

    // ---- fused epilogue ----
    const int m0 = ty * 8;
    const int tb = t0 + 2 * tx;
    float nt0 = g_nt[tb], nt1 = g_nt[tb + 1];
    float ct0 = g_ct[tb], ct1 = g_ct[tb + 1];

    float eloc[8], saloc[8];
    #pragma unroll
    for (int mi = 0; mi < 8; mi++) {
        float nqv = g_nq[m0 + mi];
        float2 s1 = upk(acc1[mi]);
        float2 s2 = upk(acc2[mi]);
        // t even
        float sq0 = fmaf(-2.0f * QV, s1.x, nqv + nt0);
        float xd0 = sqrtf(fmaxf(sq0, 0.0f));
        float e0  = KE * __expf(-xd0);
        float dt0 = s2.x - ct0;
        float a0  = e0 * dt0;
        float b0  = fmaf(e0, xd0, e0);
        // t odd
        float sq1 = fmaf(-2.0f * QV, s1.y, nqv + nt1);
        float xd1 = sqrtf(fmaxf(sq1, 0.0f));
        float e1  = KE * __expf(-xd1);
        float dt1 = s2.y - ct1;
        float a1  = e1 * dt1;
        float b1  = fmaf(e1, xd1, e1);

        float qa0 = QV * a0, qa1 = QV * a1;
        *(float2*)&g_aT[(size_t)tb * 128 + 2 * (m0 + mi)]       = make_float2(qa0, qa0);
        *(float2*)&g_aT[(size_t)(tb + 1) * 128 + 2 * (m0 + mi)] = make_float2(qa1, qa1);
        *(float2*)&g_bT[(size_t)tb * 128 + 2 * (m0 + mi)]       = make_float2(b0, b0);
        *(float2*)&g_bT[(size_t)(tb + 1) * 128 + 2 * (m0 + mi)] = make_float2(b1, b1);

        eloc[mi] = fmaf(b0, dt0, b1 * dt1);
        saloc[mi] = a0 + a1;
    }

    // per-block E/sa reduction (reuse As smem)
    __syncthreads();
    float* Es = &As[0][0];          // 64 m x 32 lanes
    float* Ss = &As[0][0] + 2048;
    #pragma unroll
    for (int mi = 0; mi < 8; mi++) {
        Es[(m0 + mi) * 32 + tx] = eloc[mi];
        Ss[(m0 + mi) * 32 + tx] = saloc[mi];
    }
    __syncthreads();
    if (tid < 64) {
        float se = 0.0f, ss = 0.0f;
        #pragma unroll
        for (int x = 0; x < 32; x++) { se += Es[tid * 32 + x]; ss += Ss[tid * 32 + x]; }
        g_Ep[blockIdx.x * NM + tid] = se;
        g_sa[blockIdx.x * NM + tid] = ss;
    }
}

// ---------------- GEMM2: 256 thr, tile 64m x 128p, frag 8m x 4p, warp-uniform m ----------------
__global__ __launch_bounds__(256, 2)
void gemm2_kernel(const float* __restrict__ xt, const float* __restrict__ jx) {
    __shared__ float Aa[2][8 * 128];    // dup [t][2m]
    __shared__ float Ab[2][8 * 128];
    __shared__ float Bx[2][8 * 128];    // [t][p]
    __shared__ float Bj[2][8 * 128];

    const int tid = threadIdx.x;
    const int tx = tid & 31;            // 4 p at p0+4*tx
    const int ty = tid >> 5;            // 8 m at 8*ty (warp-uniform)
    const int p0 = blockIdx.x * 128;
    const int t0 = blockIdx.y * 64;
    const int NKT = 8;

    u64 acc1[8], acc2[8];
    #pragma unroll
    for (int i = 0; i < 8; i++) { acc1[i] = 0ull; acc2[i] = 0ull; }

    auto cp_tile = [&](int kt, int buf) {
        int tt0 = t0 + kt * 8;
        int row = tid >> 5, col4 = (tid & 31) * 4;
        int tg = tt0 + row;
        int okA = (tg < NTPAD) ? 16 : 0;
        const float* ap = okA ? &g_aT[(size_t)tg * 128 + col4] : g_aT;
        const float* bp = okA ? &g_bT[(size_t)tg * 128 + col4] : g_bT;
        cp16(&Aa[buf][row * 128 + col4], ap, okA);
        cp16(&Ab[buf][row * 128 + col4], bp, okA);
        int pc = p0 + col4;
        int okB = (tg < NT && pc < NP) ? 16 : 0;
        const float* xp = okB ? &xt[(size_t)tg * NP + pc] : xt;
        const float* jp = okB ? &jx[(size_t)tg * NP + pc] : jx;
        cp16(&Bx[buf][row * 128 + col4], xp, okB);
        cp16(&Bj[buf][row * 128 + col4], jp, okB);
        cp_commit();
    };

    cp_tile(0, 0);
    cp_wait0();
    __syncthreads();

    for (int kt = 0; kt < NKT; kt++) {
        const int cur = kt & 1;
        if (kt + 1 < NKT) cp_tile(kt + 1, cur ^ 1);

        #pragma unroll
        for (int k = 0; k < 8; k++) {
            ulonglong2 a0 = *(const ulonglong2*)&Aa[cur][k * 128 + 16 * ty];
            ulonglong2 a1 = *(const ulonglong2*)&Aa[cur][k * 128 + 16 * ty + 4];
            ulonglong2 a2 = *(const ulonglong2*)&Aa[cur][k * 128 + 16 * ty + 8];
            ulonglong2 a3 = *(const ulonglong2*)&Aa[cur][k * 128 + 16 * ty + 12];
            ulonglong2 b0 = *(const ulonglong2*)&Ab[cur][k * 128 + 16 * ty];
            ulonglong2 b1 = *(const ulonglong2*)&Ab[cur][k * 128 + 16 * ty + 4];
            ulonglong2 b2 = *(const ulonglong2*)&Ab[cur][k * 128 + 16 * ty + 8];
            ulonglong2 b3 = *(const ulonglong2*)&Ab[cur][k * 128 + 16 * ty + 12];
            ulonglong2 X = *(const ulonglong2*)&Bx[cur][k * 128 + 4 * tx];
            ulonglong2 J = *(const ulonglong2*)&Bj[cur][k * 128 + 4 * tx];
            u64 Ap[8] = {a0.x, a0.y, a1.x, a1.y, a2.x, a2.y, a3.x, a3.y};
            u64 Bp[8] = {b0.x, b0.y, b1.x, b1.y, b2.x, b2.y, b3.x, b3.y};
            #pragma unroll
            for (int mi = 0; mi < 8; mi++) {
                ffma2(acc1[mi], Ap[mi], X.x);
                ffma2(acc2[mi], Ap[mi], X.y);
            }
            #pragma unroll
            for (int mi = 0; mi < 8; mi++) {
                ffma2(acc1[mi], Bp[mi], J.x);
                ffma2(acc2[mi], Bp[mi], J.y);
            }
        }
        if (kt + 1 < NKT) cp_wait0();
        __syncthreads();
    }

    const int m0 = ty * 8;
    #pragma unroll
    for (int mi = 0; mi < 8; mi++) {
        float2 u0 = upk(acc1[mi]);
        float2 u1 = upk(acc2[mi]);
        size_t base = ((size_t)blockIdx.y * NM + (m0 + mi)) * G2_PPAD;
        *(float4*)&g_F2[base + p0 + 4 * tx] = make_float4(-u0.x, -u0.y, -u1.x, -u1.y);
    }
}

// ---------------- final ----------------
__global__ void final_kernel(const float* __restrict__ Rs, float* __restrict__ out) {
    __shared__ float Fxs[NP];
    __shared__ float ssa;
    const int m = blockIdx.x;
    const int tid = threadIdx.x;

    if (tid < 32) {
        float s = 0.0f;
        for (int b = tid; b < G1_TT; b += 32) s += g_sa[b * NM + m];
        #pragma unroll
        for (int o = 16; o > 0; o >>= 1) s += __shfl_xor_sync(0xffffffffu, s, o);
        if (tid == 0) ssa = s;
    } else if (tid < 64) {
        int l = tid - 32;
        float e = 0.0f;
        for (int b = l; b < G1_TT; b += 32) e += g_Ep[b * NM + m];
        #pragma unroll
        for (int o = 16; o > 0; o >>= 1) e += __shfl_xor_sync(0xffffffffu, e, o);
        if (l == 0) out[m] = e / QV;
    }
    __syncthreads();

    if (tid < NP) {
        float F = ssa * g_qxs[m * NP + tid];
        #pragma unroll 7
        for (int ks = 0; ks < G2_KS; ks++)
            F += g_F2[((size_t)ks * NM + m) * G2_PPAD + tid];
        Fxs[tid] = F * g_xs3[m * NP + tid];
    }
    __syncthreads();

    if (tid < NA * 3) {
        int a = tid / 3, c = tid % 3;
        float Ra = Rs[(m * NA + a) * 3 + c];
        float acc = 0.0f;
        #pragma unroll
        for (int bb = 0; bb < NA; bb++) {
            if (bb == a) continue;
            int hi = (a > bb) ? a : bb;
            int lo = (a > bb) ? bb : a;
            int p = hi * (hi - 1) / 2 + lo;
            float Rb = Rs[(m * NA + bb) * 3 + c];
            acc += (Rb - Ra) * Fxs[p];
        }
        out[NM + m * NA * 3 + tid] = acc;
    }
}

extern "C" void kernel_launch(void* const* d_in, const int* in_sizes, int n_in,
                              void* d_out, int out_size) {
    const float* Rs = (const float*)d_in[0];
    const float* xs_train = (const float*)d_in[1];
    const float* Jx = (const float*)d_in[2];
    float* out = (float*)d_out;

    prep_kernel<<<NM + NTPAD / 8, 256>>>(Rs, xs_train, Jx);
    gemm1f_kernel<<<G1_TT, 256>>>(xs_train, Jx);
    gemm2_kernel<<<dim3(G2_PT, G2_KS), 256>>>(xs_train, Jx);
    final_kernel<<<NM, 288>>>(Rs, out);
}

// round 12
// speedup vs baseline: 1.0581x; 1.0581x over previous
#include <cuda_runtime.h>
#include <math.h>

#define NM 64
#define NA 24
#define NP 276
#define NPPAD 288
#define NT 6000
#define NTPAD 6016
#define QV 0.22360679774997896f
#define KE 0.016666666666666666f

#define G1_TT 94        // t-tiles of 64 (fused gemm1+epilogue)
#define G2_PT 3         // p-tiles of 128 (PPAD 384)
#define G2_KS 98        // t-splits, chunk 64 (8 k-tiles of 8)
#define G2_PPAD 384

typedef unsigned long long u64;

// ---------------- static device scratch ----------------
__device__ float g_qxs[NM * NP];
__device__ float g_xs3[NM * NP];
__device__ float g_nq[NM];
__device__ float g_qxsTd[NPPAD * 128];         // qxs transposed + dup [p][2m]
__device__ float g_nt[NTPAD];
__device__ float g_ct[NTPAD];
__device__ float g_aT[NTPAD * 128];            // (q a) transposed + dup [t][2m]
__device__ float g_bT[NTPAD * 128];
__device__ float g_Ep[G1_TT * NM];
__device__ float g_sa[G1_TT * NM];
__device__ float g_F2[G2_KS * NM * G2_PPAD];

__device__ __forceinline__ void ffma2(u64& c, u64 a, u64 b) {
    asm("fma.rn.f32x2 %0, %1, %2, %0;" : "+l"(c) : "l"(a), "l"(b));
}
__device__ __forceinline__ float2 upk(u64 v) {
    float2 f;
    asm("mov.b64 {%0, %1}, %2;" : "=f"(f.x), "=f"(f.y) : "l"(v));
    return f;
}
__device__ __forceinline__ void cp16(void* smem, const void* gptr, int bytes) {
    unsigned s = (unsigned)__cvta_generic_to_shared(smem);
    asm volatile("cp.async.ca.shared.global [%0], [%1], 16, %2;\n"
                 :: "r"(s), "l"(gptr), "r"(bytes));
}
__device__ __forceinline__ void cp_commit() {
    asm volatile("cp.async.commit_group;\n" ::: "memory");
}
__device__ __forceinline__ void cp_wait0() {
    asm volatile("cp.async.wait_group 0;\n" ::: "memory");
}

__device__ __forceinline__ void pair_ij(int p, int& i, int& j) {
    int ii = (int)((1.0f + sqrtf(1.0f + 8.0f * (float)p)) * 0.5f);
    while (ii * (ii - 1) / 2 > p) ii--;
    while ((ii + 1) * ii / 2 <= p) ii++;
    i = ii;
    j = p - ii * (ii - 1) / 2;
}

// ---------------- fused prep ----------------
__global__ void prep_kernel(const float* __restrict__ Rs,
                            const float* __restrict__ xt,
                            const float* __restrict__ jx) {
    const int tid = threadIdx.x;
    if (blockIdx.x < NM) {
        __shared__ float red[256];
        const int m = blockIdx.x;
        float ssum = 0.0f;
        #pragma unroll
        for (int rep = 0; rep < 2; rep++) {
            int p = tid + 256 * rep;
            if (p < NP) {
                int i, j;
                pair_ij(p, i, j);
                float dx = Rs[(m * NA + i) * 3 + 0] - Rs[(m * NA + j) * 3 + 0];
                float dy = Rs[(m * NA + i) * 3 + 1] - Rs[(m * NA + j) * 3 + 1];
                float dz = Rs[(m * NA + i) * 3 + 2] - Rs[(m * NA + j) * 3 + 2];
                float d = sqrtf(dx * dx + dy * dy + dz * dz);
                float xs = 1.0f / d;
                float qv = QV * xs;
                g_qxs[m * NP + p] = qv;
                g_xs3[m * NP + p] = xs * xs * xs;
                *(float2*)&g_qxsTd[p * 128 + 2 * m] = make_float2(qv, qv);
                ssum += qv * qv;
            } else if (p < NPPAD) {
                *(float2*)&g_qxsTd[p * 128 + 2 * m] = make_float2(0.0f, 0.0f);
            }
        }
        red[tid] = ssum;
        __syncthreads();
        if (tid < 32) {
            float s = red[tid];
            #pragma unroll
            for (int k = 1; k < 8; k++) s += red[tid + 32 * k];
            #pragma unroll
            for (int o = 16; o > 0; o >>= 1) s += __shfl_xor_sync(0xffffffffu, s, o);
            if (tid == 0) g_nq[m] = s;
        }
        return;
    }
    int w = ((blockIdx.x - NM) * blockDim.x + tid) >> 5;
    int lane = tid & 31;
    if (w >= NTPAD) return;
    if (w >= NT) {
        if (lane == 0) { g_nt[w] = 0.0f; g_ct[w] = 0.0f; }
        return;
    }
    const float* xr = xt + (size_t)w * NP;
    const float* jr = jx + (size_t)w * NP;
    float sn = 0.0f, sc = 0.0f;
    #pragma unroll
    for (int k = 0; k < 9; k++) {
        int p = lane + 32 * k;
        if (p < NP) {
            float x = xr[p];
            sn = fmaf(x, x, sn);
            sc = fmaf(x, jr[p], sc);
        }
    }
    #pragma unroll
    for (int o = 16; o > 0; o >>= 1) {
        sn += __shfl_xor_sync(0xffffffffu, sn, o);
        sc += __shfl_xor_sync(0xffffffffu, sc, o);
    }
    if (lane == 0) {
        g_nt[w] = QV * QV * sn;
        g_ct[w] = QV * sc;
    }
}

// ---------------- fused GEMM1 + epilogue: 256 thr, tile 64m x 64t, full K=288 ----------------
__global__ __launch_bounds__(256)
void gemm1f_kernel(const float* __restrict__ xt, const float* __restrict__ jx) {
    __shared__ float As[2][16 * 128];   // dup A [k][2m]
    __shared__ float Bx[2][16 * 66];    // [k][t]
    __shared__ float Bj[2][16 * 66];

    const int tid = threadIdx.x;
    const int tx = tid & 31;            // t-pair at 2*tx
    const int ty = tid >> 5;            // 8 m at 8*ty (warp-uniform)
    const int t0 = blockIdx.x * 64;
    const int NKT = 18;

    const int lbt = tid >> 2;
    const int lbc = tid & 3;

    u64 acc1[8], acc2[8];
    #pragma unroll
    for (int i = 0; i < 8; i++) { acc1[i] = 0ull; acc2[i] = 0ull; }

    float4 xv, jv;

    auto cpA = [&](int kt, int buf) {
        int k0 = kt * 16;
        #pragma unroll
        for (int c = 0; c < 2; c++) {
            int idx = tid + 256 * c;
            int row = idx >> 5, col = idx & 31;
            cp16(&As[buf][row * 128 + col * 4], &g_qxsTd[(k0 + row) * 128 + col * 4], 16);
        }
        cp_commit();
    };
    auto ldgB = [&](int kt) {
        int k0 = kt * 16;
        int kk = k0 + 4 * lbc;
        int tg = t0 + lbt;
        xv = make_float4(0.f, 0.f, 0.f, 0.f);
        jv = make_float4(0.f, 0.f, 0.f, 0.f);
        if (tg < NT && kk < NP) {
            xv = *(const float4*)&xt[(size_t)tg * NP + kk];
            jv = *(const float4*)&jx[(size_t)tg * NP + kk];
        }
    };
    auto stsB = [&](int buf) {
        Bx[buf][(4 * lbc + 0) * 66 + lbt] = xv.x;
        Bx[buf][(4 * lbc + 1) * 66 + lbt] = xv.y;
        Bx[buf][(4 * lbc + 2) * 66 + lbt] = xv.z;
        Bx[buf][(4 * lbc + 3) * 66 + lbt] = xv.w;
        Bj[buf][(4 * lbc + 0) * 66 + lbt] = jv.x;
        Bj[buf][(4 * lbc + 1) * 66 + lbt] = jv.y;
        Bj[buf][(4 * lbc + 2) * 66 + lbt] = jv.z;
        Bj[buf][(4 * lbc + 3) * 66 + lbt] = jv.w;
    };

    ldgB(0);
    cpA(0, 0);
    stsB(0);
    ldgB(1);
    cp_wait0();
    __syncthreads();

    for (int kt = 0; kt < NKT; kt++) {
        const int cur = kt & 1;
        if (kt + 1 < NKT) {
            stsB(cur ^ 1);
            cpA(kt + 1, cur ^ 1);
        }
        if (kt + 2 < NKT) ldgB(kt + 2);

        #pragma unroll
        for (int k = 0; k < 16; k++) {
            ulonglong2 a0 = *(const ulonglong2*)&As[cur][k * 128 + 16 * ty];
            ulonglong2 a1 = *(const ulonglong2*)&As[cur][k * 128 + 16 * ty + 4];
            ulonglong2 a2 = *(const ulonglong2*)&As[cur][k * 128 + 16 * ty + 8];
            ulonglong2 a3 = *(const ulonglong2*)&As[cur][k * 128 + 16 * ty + 12];
            u64 X = *(const u64*)&Bx[cur][k * 66 + 2 * tx];
            u64 J = *(const u64*)&Bj[cur][k * 66 + 2 * tx];
            u64 Ap[8] = {a0.x, a0.y, a1.x, a1.y, a2.x, a2.y, a3.x, a3.y};
            #pragma unroll
            for (int mi = 0; mi < 8; mi++) {
                ffma2(acc1[mi], Ap[mi], X);
                ffma2(acc2[mi], Ap[mi], J);
            }
        }
        if (kt + 1 < NKT) cp_wait0();
        __syncthreads();
    }

    // ---- fused epilogue ----
    const int m0 = ty * 8;
    const int tb = t0 + 2 * tx;
    float nt0 = g_nt[tb], nt1 = g_nt[tb + 1];
    float ct0 = g_ct[tb], ct1 = g_ct[tb + 1];

    float eloc[8], saloc[8];
    #pragma unroll
    for (int mi = 0; mi < 8; mi++) {
        float nqv = g_nq[m0 + mi];
        float2 s1 = upk(acc1[mi]);
        float2 s2 = upk(acc2[mi]);
        float sq0 = fmaf(-2.0f * QV, s1.x, nqv + nt0);
        float xd0 = sqrtf(fmaxf(sq0, 0.0f));
        float e0  = KE * __expf(-xd0);
        float dt0 = s2.x - ct0;
        float a0  = e0 * dt0;
        float b0  = fmaf(e0, xd0, e0);
        float sq1 = fmaf(-2.0f * QV, s1.y, nqv + nt1);
        float xd1 = sqrtf(fmaxf(sq1, 0.0f));
        float e1  = KE * __expf(-xd1);
        float dt1 = s2.y - ct1;
        float a1  = e1 * dt1;
        float b1  = fmaf(e1, xd1, e1);

        float qa0 = QV * a0, qa1 = QV * a1;
        *(float2*)&g_aT[(size_t)tb * 128 + 2 * (m0 + mi)]       = make_float2(qa0, qa0);
        *(float2*)&g_aT[(size_t)(tb + 1) * 128 + 2 * (m0 + mi)] = make_float2(qa1, qa1);
        *(float2*)&g_bT[(size_t)tb * 128 + 2 * (m0 + mi)]       = make_float2(b0, b0);
        *(float2*)&g_bT[(size_t)(tb + 1) * 128 + 2 * (m0 + mi)] = make_float2(b1, b1);

        eloc[mi] = fmaf(b0, dt0, b1 * dt1);
        saloc[mi] = a0 + a1;
    }

    __syncthreads();
    float* Es = &As[0][0];
    float* Ss = &As[0][0] + 2048;
    #pragma unroll
    for (int mi = 0; mi < 8; mi++) {
        Es[(m0 + mi) * 32 + tx] = eloc[mi];
        Ss[(m0 + mi) * 32 + tx] = saloc[mi];
    }
    __syncthreads();
    if (tid < 64) {
        float se = 0.0f, ss = 0.0f;
        #pragma unroll
        for (int x = 0; x < 32; x++) { se += Es[tid * 32 + x]; ss += Ss[tid * 32 + x]; }
        g_Ep[blockIdx.x * NM + tid] = se;
        g_sa[blockIdx.x * NM + tid] = ss;
    }
}

// ---------------- GEMM2: 256 thr, tile 64m x 128p, frag 8m x 4p, warp-uniform m ----------------
__global__ __launch_bounds__(256, 2)
void gemm2_kernel(const float* __restrict__ xt, const float* __restrict__ jx) {
    __shared__ float Aa[2][8 * 128];
    __shared__ float Ab[2][8 * 128];
    __shared__ float Bx[2][8 * 128];
    __shared__ float Bj[2][8 * 128];

    const int tid = threadIdx.x;
    const int tx = tid & 31;
    const int ty = tid >> 5;
    const int p0 = blockIdx.x * 128;
    const int t0 = blockIdx.y * 64;
    const int NKT = 8;

    u64 acc1[8], acc2[8];
    #pragma unroll
    for (int i = 0; i < 8; i++) { acc1[i] = 0ull; acc2[i] = 0ull; }

    auto cp_tile = [&](int kt, int buf) {
        int tt0 = t0 + kt * 8;
        int row = tid >> 5, col4 = (tid & 31) * 4;
        int tg = tt0 + row;
        int okA = (tg < NTPAD) ? 16 : 0;
        const float* ap = okA ? &g_aT[(size_t)tg * 128 + col4] : g_aT;
        const float* bp = okA ? &g_bT[(size_t)tg * 128 + col4] : g_bT;
        cp16(&Aa[buf][row * 128 + col4], ap, okA);
        cp16(&Ab[buf][row * 128 + col4], bp, okA);
        int pc = p0 + col4;
        int okB = (tg < NT && pc < NP) ? 16 : 0;
        const float* xp = okB ? &xt[(size_t)tg * NP + pc] : xt;
        const float* jp = okB ? &jx[(size_t)tg * NP + pc] : jx;
        cp16(&Bx[buf][row * 128 + col4], xp, okB);
        cp16(&Bj[buf][row * 128 + col4], jp, okB);
        cp_commit();
    };

    cp_tile(0, 0);
    cp_wait0();
    __syncthreads();

    for (int kt = 0; kt < NKT; kt++) {
        const int cur = kt & 1;
        if (kt + 1 < NKT) cp_tile(kt + 1, cur ^ 1);

        #pragma unroll
        for (int k = 0; k < 8; k++) {
            ulonglong2 a0 = *(const ulonglong2*)&Aa[cur][k * 128 + 16 * ty];
            ulonglong2 a1 = *(const ulonglong2*)&Aa[cur][k * 128 + 16 * ty + 4];
            ulonglong2 a2 = *(const ulonglong2*)&Aa[cur][k * 128 + 16 * ty + 8];
            ulonglong2 a3 = *(const ulonglong2*)&Aa[cur][k * 128 + 16 * ty + 12];
            ulonglong2 b0 = *(const ulonglong2*)&Ab[cur][k * 128 + 16 * ty];
            ulonglong2 b1 = *(const ulonglong2*)&Ab[cur][k * 128 + 16 * ty + 4];
            ulonglong2 b2 = *(const ulonglong2*)&Ab[cur][k * 128 + 16 * ty + 8];
            ulonglong2 b3 = *(const ulonglong2*)&Ab[cur][k * 128 + 16 * ty + 12];
            ulonglong2 X = *(const ulonglong2*)&Bx[cur][k * 128 + 4 * tx];
            ulonglong2 J = *(const ulonglong2*)&Bj[cur][k * 128 + 4 * tx];
            u64 Ap[8] = {a0.x, a0.y, a1.x, a1.y, a2.x, a2.y, a3.x, a3.y};
            u64 Bp[8] = {b0.x, b0.y, b1.x, b1.y, b2.x, b2.y, b3.x, b3.y};
            #pragma unroll
            for (int mi = 0; mi < 8; mi++) {
                ffma2(acc1[mi], Ap[mi], X.x);
                ffma2(acc2[mi], Ap[mi], X.y);
            }
            #pragma unroll
            for (int mi = 0; mi < 8; mi++) {
                ffma2(acc1[mi], Bp[mi], J.x);
                ffma2(acc2[mi], Bp[mi], J.y);
            }
        }
        if (kt + 1 < NKT) cp_wait0();
        __syncthreads();
    }

    const int m0 = ty * 8;
    #pragma unroll
    for (int mi = 0; mi < 8; mi++) {
        float2 u0 = upk(acc1[mi]);
        float2 u1 = upk(acc2[mi]);
        size_t base = ((size_t)blockIdx.y * NM + (m0 + mi)) * G2_PPAD;
        *(float4*)&g_F2[base + p0 + 4 * tx] = make_float4(-u0.x, -u0.y, -u1.x, -u1.y);
    }
}

// ---------------- final: MLP-batched partial reduction + scatter ----------------
__global__ void final_kernel(const float* __restrict__ Rs, float* __restrict__ out) {
    __shared__ float Fxs[NP];
    __shared__ float ssa;
    const int m = blockIdx.x;
    const int tid = threadIdx.x;

    if (tid < 32) {
        float s = 0.0f;
        for (int b = tid; b < G1_TT; b += 32) s += g_sa[b * NM + m];
        #pragma unroll
        for (int o = 16; o > 0; o >>= 1) s += __shfl_xor_sync(0xffffffffu, s, o);
        if (tid == 0) ssa = s;
    } else if (tid < 64) {
        int l = tid - 32;
        float e = 0.0f;
        for (int b = l; b < G1_TT; b += 32) e += g_Ep[b * NM + m];
        #pragma unroll
        for (int o = 16; o > 0; o >>= 1) e += __shfl_xor_sync(0xffffffffu, e, o);
        if (l == 0) out[m] = e / QV;
    }
    __syncthreads();

    if (tid < NP) {
        float F = ssa * g_qxs[m * NP + tid];
        // 98 partials: 16-wide MLP batches (6x16 + 2)
        #pragma unroll
        for (int ks0 = 0; ks0 < 96; ks0 += 16) {
            float t[16];
            #pragma unroll
            for (int i = 0; i < 16; i++)
                t[i] = g_F2[((size_t)(ks0 + i) * NM + m) * G2_PPAD + tid];
            #pragma unroll
            for (int i = 0; i < 16; i++) F += t[i];
        }
        {
            float t0 = g_F2[((size_t)96 * NM + m) * G2_PPAD + tid];
            float t1 = g_F2[((size_t)97 * NM + m) * G2_PPAD + tid];
            F += t0 + t1;
        }
        Fxs[tid] = F * g_xs3[m * NP + tid];
    }
    __syncthreads();

    if (tid < NA * 3) {
        int a = tid / 3, c = tid % 3;
        float Ra = Rs[(m * NA + a) * 3 + c];
        float acc = 0.0f;
        #pragma unroll
        for (int bb = 0; bb < NA; bb++) {
            if (bb == a) continue;
            int hi = (a > bb) ? a : bb;
            int lo = (a > bb) ? bb : a;
            int p = hi * (hi - 1) / 2 + lo;
            float Rb = Rs[(m * NA + bb) * 3 + c];
            acc += (Rb - Ra) * Fxs[p];
        }
        out[NM + m * NA * 3 + tid] = acc;
    }
}

extern "C" void kernel_launch(void* const* d_in, const int* in_sizes, int n_in,
                              void* d_out, int out_size) {
    const float* Rs = (const float*)d_in[0];
    const float* xs_train = (const float*)d_in[1];
    const float* Jx = (const float*)d_in[2];
    float* out = (float*)d_out;

    prep_kernel<<<NM + NTPAD / 8, 256>>>(Rs, xs_train, Jx);
    gemm1f_kernel<<<G1_TT, 256>>>(xs_train, Jx);
    gemm2_kernel<<<dim3(G2_PT, G2_KS), 256>>>(xs_train, Jx);
    final_kernel<<<NM, 288>>>(Rs, out);
}